// round 2
// baseline (speedup 1.0000x reference)
#include <cuda_runtime.h>
#include <cstdint>

#define NTOK 98
#define CDIM 192
#define NH   6
#define HD   32
#define NWIN 64
#define BTOT 4096
#define ROWS (BTOT*NTOK)          // 401408
#define QKVN (3*CDIM)             // 576
#define PER_TENSOR (BTOT*NH*NTOK*HD)   // 77,070,336

// ---- scratch (static device allocations are the sanctioned workaround) ----
__device__ float g_q[PER_TENSOR];
__device__ float g_k[PER_TENSOR];
__device__ float g_v[PER_TENSOR];
__device__ float g_o[ROWS*CDIM];           // attention output, (b, n, C) layout
__device__ float g_bias[NH*NTOK*NTOK];     // gathered relative-position bias

// ============================================================
// Kernel 1: gather relative position bias  bias[h][i][j] = table[rel[i][j]*NH + h]
// ============================================================
__global__ void bias_gather(const float* __restrict__ table, const int* __restrict__ rel) {
    int idx = blockIdx.x * blockDim.x + threadIdx.x;
    if (idx < NH * NTOK * NTOK) {
        int h  = idx / (NTOK * NTOK);
        int ij = idx - h * (NTOK * NTOK);
        g_bias[idx] = table[rel[ij] * NH + h];
    }
}

// ============================================================
// Kernel 2: QKV GEMM.  C[m][nn] = sum_k x[m][k] * W[nn][k] + b[nn]
// M=401408, N=576, K=192.  Tile 128x64x16, 256 threads, 8x4 per thread.
// Epilogue scatters into g_q/g_k/g_v with layout (b, h, n, d); q scaled.
// ============================================================
__global__ __launch_bounds__(256)
void qkv_gemm(const float* __restrict__ A, const float* __restrict__ W,
              const float* __restrict__ bvec) {
    __shared__ float As[16 * 128];
    __shared__ float Bs[16 * 64];

    const int tid    = threadIdx.x;
    const int blockM = blockIdx.x * 128;
    const int blockN = blockIdx.y * 64;

    const int ar = tid >> 2;          // 0..63
    const int ac = (tid & 3) << 2;    // 0,4,8,12

    const float* Ag0 = A + (size_t)(blockM + ar)      * CDIM + ac;
    const float* Ag1 = A + (size_t)(blockM + ar + 64) * CDIM + ac;
    const float* Wg  = W + (size_t)(blockN + ar)      * CDIM + ac;

    const int tx = tid & 15;          // N dir (x4)
    const int ty = tid >> 4;          // M dir (x8)

    float acc[8][4];
#pragma unroll
    for (int i = 0; i < 8; i++)
#pragma unroll
        for (int j = 0; j < 4; j++) acc[i][j] = 0.f;

    for (int k0 = 0; k0 < CDIM; k0 += 16) {
        float4 a0 = *(const float4*)(Ag0 + k0);
        float4 a1 = *(const float4*)(Ag1 + k0);
        float4 w0 = *(const float4*)(Wg  + k0);

        As[(ac + 0) * 128 + ar] = a0.x;
        As[(ac + 1) * 128 + ar] = a0.y;
        As[(ac + 2) * 128 + ar] = a0.z;
        As[(ac + 3) * 128 + ar] = a0.w;
        As[(ac + 0) * 128 + ar + 64] = a1.x;
        As[(ac + 1) * 128 + ar + 64] = a1.y;
        As[(ac + 2) * 128 + ar + 64] = a1.z;
        As[(ac + 3) * 128 + ar + 64] = a1.w;
        Bs[(ac + 0) * 64 + ar] = w0.x;
        Bs[(ac + 1) * 64 + ar] = w0.y;
        Bs[(ac + 2) * 64 + ar] = w0.z;
        Bs[(ac + 3) * 64 + ar] = w0.w;
        __syncthreads();

#pragma unroll
        for (int k = 0; k < 16; k++) {
            float4 av0 = *(const float4*)&As[k * 128 + ty * 8];
            float4 av1 = *(const float4*)&As[k * 128 + ty * 8 + 4];
            float4 bv  = *(const float4*)&Bs[k * 64  + tx * 4];
            float a[8] = {av0.x, av0.y, av0.z, av0.w, av1.x, av1.y, av1.z, av1.w};
            float b[4] = {bv.x, bv.y, bv.z, bv.w};
#pragma unroll
            for (int i = 0; i < 8; i++)
#pragma unroll
                for (int j = 0; j < 4; j++)
                    acc[i][j] += a[i] * b[j];
        }
        __syncthreads();
    }

    const float scale = 0.17677669529663687f;  // 32^-0.5
#pragma unroll
    for (int i = 0; i < 8; i++) {
        int row = blockM + ty * 8 + i;
        int b   = row / NTOK;
        int n   = row - b * NTOK;
#pragma unroll
        for (int j = 0; j < 4; j++) {
            int nn  = blockN + tx * 4 + j;
            float v = acc[i][j] + bvec[nn];
            int t   = nn / CDIM;
            int rem = nn - t * CDIM;
            int hh  = rem >> 5;
            int d   = rem & 31;
            size_t off = (((size_t)b * NH + hh) * NTOK + n) * HD + d;
            if (t == 0)      g_q[off] = v * scale;
            else if (t == 1) g_k[off] = v;
            else             g_v[off] = v;
        }
    }
}

// ============================================================
// Kernel 3: attention. One CTA per (b, h). 4 warps; each warp owns q-rows
// i = warp, warp+4, ... K,V staged in smem (pitch 36 for conflict-free +
// float4-aligned access). Softmax fused with bias + window mask.
// Output written in (b, n, C) layout -> free transpose for proj GEMM.
// ============================================================
__global__ __launch_bounds__(128)
void attn_kernel(const float* __restrict__ mask) {
    __shared__ float Ks[NTOK * 36];
    __shared__ float Vs[NTOK * 36];
    __shared__ float probs[4][NTOK + 2];
    __shared__ float qrow[4][32];

    const int bh = blockIdx.x;
    const int b  = bh / NH;
    const int h  = bh - b * NH;
    const int w  = b & (NWIN - 1);       // window index = b % 64

    const float* Kp = g_k + (size_t)bh * NTOK * HD;
    const float* Vp = g_v + (size_t)bh * NTOK * HD;
    const float* Qp = g_q + (size_t)bh * NTOK * HD;

    const int tid = threadIdx.x;
    for (int idx = tid; idx < NTOK * HD; idx += 128) {
        int j = idx >> 5, d = idx & 31;
        Ks[j * 36 + d] = Kp[idx];
        Vs[j * 36 + d] = Vp[idx];
    }
    __syncthreads();

    const int warp = tid >> 5, lane = tid & 31;
    const float* biasH = g_bias + (size_t)h * NTOK * NTOK;
    const float* maskW = mask   + (size_t)w * NTOK * NTOK;

    for (int i = warp; i < NTOK; i += 4) {
        qrow[warp][lane] = Qp[i * HD + lane];
        __syncwarp();

        const float* bm = biasH + i * NTOK;
        const float* mk = maskW + i * NTOK;

        float s[4];
#pragma unroll
        for (int t = 0; t < 4; t++) {
            int j = lane + t * 32;
            if (j < NTOK) {
                float acc = 0.f;
#pragma unroll
                for (int d4 = 0; d4 < 8; d4++) {
                    float4 kv = *(const float4*)&Ks[j * 36 + d4 * 4];
                    float4 qv = *(const float4*)&qrow[warp][d4 * 4];
                    acc += kv.x * qv.x + kv.y * qv.y + kv.z * qv.z + kv.w * qv.w;
                }
                s[t] = acc + bm[j] + mk[j];
            } else {
                s[t] = -1e30f;
            }
        }

        float m = fmaxf(fmaxf(s[0], s[1]), fmaxf(s[2], s[3]));
#pragma unroll
        for (int off = 16; off; off >>= 1)
            m = fmaxf(m, __shfl_xor_sync(0xffffffffu, m, off));

        float sum = 0.f;
#pragma unroll
        for (int t = 0; t < 4; t++) {
            int j = lane + t * 32;
            s[t] = (j < NTOK) ? __expf(s[t] - m) : 0.f;
            sum += s[t];
        }
#pragma unroll
        for (int off = 16; off; off >>= 1)
            sum += __shfl_xor_sync(0xffffffffu, sum, off);

        float inv = 1.0f / sum;
#pragma unroll
        for (int t = 0; t < 4; t++) {
            int j = lane + t * 32;
            if (j < NTOK) probs[warp][j] = s[t] * inv;
        }
        __syncwarp();

        float o = 0.f;
#pragma unroll 2
        for (int j = 0; j < NTOK; j++)
            o += probs[warp][j] * Vs[j * 36 + lane];

        g_o[((size_t)(b * NTOK + i)) * CDIM + h * HD + lane] = o;
        __syncwarp();
    }
}

// ============================================================
// Kernel 4: output projection GEMM. C = g_o @ proj_w^T + proj_b
// M=401408, N=192, K=192. Same 128x64x16 tiling.
// ============================================================
__global__ __launch_bounds__(256)
void proj_gemm(const float* __restrict__ W, const float* __restrict__ bvec,
               float* __restrict__ C) {
    __shared__ float As[16 * 128];
    __shared__ float Bs[16 * 64];

    const int tid    = threadIdx.x;
    const int blockM = blockIdx.x * 128;
    const int blockN = blockIdx.y * 64;

    const int ar = tid >> 2;
    const int ac = (tid & 3) << 2;

    const float* Ag0 = g_o + (size_t)(blockM + ar)      * CDIM + ac;
    const float* Ag1 = g_o + (size_t)(blockM + ar + 64) * CDIM + ac;
    const float* Wg  = W   + (size_t)(blockN + ar)      * CDIM + ac;

    const int tx = tid & 15;
    const int ty = tid >> 4;

    float acc[8][4];
#pragma unroll
    for (int i = 0; i < 8; i++)
#pragma unroll
        for (int j = 0; j < 4; j++) acc[i][j] = 0.f;

    for (int k0 = 0; k0 < CDIM; k0 += 16) {
        float4 a0 = *(const float4*)(Ag0 + k0);
        float4 a1 = *(const float4*)(Ag1 + k0);
        float4 w0 = *(const float4*)(Wg  + k0);

        As[(ac + 0) * 128 + ar] = a0.x;
        As[(ac + 1) * 128 + ar] = a0.y;
        As[(ac + 2) * 128 + ar] = a0.z;
        As[(ac + 3) * 128 + ar] = a0.w;
        As[(ac + 0) * 128 + ar + 64] = a1.x;
        As[(ac + 1) * 128 + ar + 64] = a1.y;
        As[(ac + 2) * 128 + ar + 64] = a1.z;
        As[(ac + 3) * 128 + ar + 64] = a1.w;
        Bs[(ac + 0) * 64 + ar] = w0.x;
        Bs[(ac + 1) * 64 + ar] = w0.y;
        Bs[(ac + 2) * 64 + ar] = w0.z;
        Bs[(ac + 3) * 64 + ar] = w0.w;
        __syncthreads();

#pragma unroll
        for (int k = 0; k < 16; k++) {
            float4 av0 = *(const float4*)&As[k * 128 + ty * 8];
            float4 av1 = *(const float4*)&As[k * 128 + ty * 8 + 4];
            float4 bv  = *(const float4*)&Bs[k * 64  + tx * 4];
            float a[8] = {av0.x, av0.y, av0.z, av0.w, av1.x, av1.y, av1.z, av1.w};
            float b[4] = {bv.x, bv.y, bv.z, bv.w};
#pragma unroll
            for (int i = 0; i < 8; i++)
#pragma unroll
                for (int j = 0; j < 4; j++)
                    acc[i][j] += a[i] * b[j];
        }
        __syncthreads();
    }

#pragma unroll
    for (int i = 0; i < 8; i++) {
        int row = blockM + ty * 8 + i;
        int nn0 = blockN + tx * 4;
        float4 o;
        o.x = acc[i][0] + bvec[nn0 + 0];
        o.y = acc[i][1] + bvec[nn0 + 1];
        o.z = acc[i][2] + bvec[nn0 + 2];
        o.w = acc[i][3] + bvec[nn0 + 3];
        *(float4*)&C[(size_t)row * CDIM + nn0] = o;
    }
}

// ============================================================
extern "C" void kernel_launch(void* const* d_in, const int* in_sizes, int n_in,
                              void* d_out, int out_size) {
    const float* x      = (const float*)d_in[0];
    const float* mask   = (const float*)d_in[1];
    const float* qkv_w  = (const float*)d_in[2];
    const float* qkv_b  = (const float*)d_in[3];
    const float* proj_w = (const float*)d_in[4];
    const float* proj_b = (const float*)d_in[5];
    const float* rpb    = (const float*)d_in[6];
    const int*   rel    = (const int*)d_in[7];
    float* out = (float*)d_out;

    bias_gather<<<(NH * NTOK * NTOK + 255) / 256, 256>>>(rpb, rel);

    dim3 g1(ROWS / 128, QKVN / 64);     // 3136 x 9
    qkv_gemm<<<g1, 256>>>(x, qkv_w, qkv_b);

    attn_kernel<<<BTOT * NH, 128>>>(mask);

    dim3 g2(ROWS / 128, CDIM / 64);     // 3136 x 3
    proj_gemm<<<g2, 256>>>(proj_w, proj_b, out);
}